// round 4
// baseline (speedup 1.0000x reference)
#include <cuda_runtime.h>
#include <cstdint>

// PlaneModel: B=8192, NV=8 (512 voxels), P=64, NS=32, HID1=16, BASE=32, OUT=13, D_IN=79
#define FULL 0xffffffffu
typedef unsigned long long u64;

__constant__ float c_w1[79*16];
__constant__ float c_b1[16];
__constant__ float c_g1[16];
__constant__ float c_be1[16];

__device__ __forceinline__ u64 dup2(float a){
    u64 r; asm("mov.b64 %0,{%1,%1};" : "=l"(r) : "f"(a)); return r;
}
__device__ __forceinline__ void upk2(u64 v, float& a, float& b){
    asm("mov.b64 {%0,%1},%2;" : "=f"(a), "=f"(b) : "l"(v));
}
__device__ __forceinline__ void fma2(u64& d, u64 a, u64 b){
    asm("fma.rn.f32x2 %0,%1,%2,%0;" : "+l"(d) : "l"(a), "l"(b));
}

__device__ __forceinline__ float wsum(float x){
    x += __shfl_xor_sync(FULL, x, 16);
    x += __shfl_xor_sync(FULL, x, 8);
    x += __shfl_xor_sync(FULL, x, 4);
    x += __shfl_xor_sync(FULL, x, 2);
    x += __shfl_xor_sync(FULL, x, 1);
    return x;
}

// h[8] packed f32x2 accumulators += x * c_w1[row][0..15]; row is a compile-time constant
template<int ROW>
__device__ __forceinline__ void accw(u64* h, float x){
    u64 xx = dup2(x);
    #pragma unroll
    for (int t = 0; t < 4; t++){
        // uniform constant-bank loads (LDCU path) — immediate offsets after unroll
        u64 w0 = *(const u64*)(c_w1 + ROW*16 + 4*t + 0);
        u64 w1 = *(const u64*)(c_w1 + ROW*16 + 4*t + 2);
        fma2(h[2*t],   xx, w0);
        fma2(h[2*t+1], xx, w1);
    }
}
// runtime-row variant for the xz loop (row = 3 + k, k unrolled so still immediate)
__device__ __forceinline__ void accr(u64* h, float x, const float* wrow){
    u64 xx = dup2(x);
    #pragma unroll
    for (int t = 0; t < 4; t++){
        u64 w0 = *(const u64*)(wrow + 4*t + 0);
        u64 w1 = *(const u64*)(wrow + 4*t + 2);
        fma2(h[2*t],   xx, w0);
        fma2(h[2*t+1], xx, w1);
    }
}

#define ZSTRIDE 36   // 32 cols + 4 pad: STS conflict-free; LDS.128 readback conflict-free

__global__ void __launch_bounds__(256, 4)
plane_kernel(const float* __restrict__ g_pos,  const float* __restrict__ g_quat,
             const float* __restrict__ g_xz,   const float* __restrict__ g_aabb,
             const int*   __restrict__ g_widx, const float* __restrict__ g_pls,
             const float* __restrict__ g_w2a,  const float* __restrict__ g_b2a,
             const float* __restrict__ g_g2a,  const float* __restrict__ g_be2a,
             const float* __restrict__ g_w2b,  const float* __restrict__ g_b2b,
             const float* __restrict__ g_g2b,  const float* __restrict__ g_be2b,
             const float* __restrict__ g_wout, const float* __restrict__ g_bout,
             float* __restrict__ g_out)
{
    __shared__ __align__(16) float s_z[8][32*ZSTRIDE];

    const int tid = threadIdx.x;
    const int warp = tid >> 5, lane = tid & 31;
    const int b = (blockIdx.x << 3) + warp;
    float* sz = s_z[warp];

    const int idx = __ldg(g_widx + b*32 + lane);
    const float* xzb = g_xz + ((size_t)b << 15);   // b * 512 * 64

    // ---- phase 0 staging: cols 0..31 of the 32 gathered rows ----
    #pragma unroll
    for (int r = 0; r < 32; r++){
        int ir = __shfl_sync(FULL, idx, r);
        sz[r*ZSTRIDE + lane] = __ldcs(xzb + (ir << 6) + lane);
    }

    // ---- pose math overlaps the staging LDG latency ----
    float qx = __ldg(g_quat + b*4 + 0), qy = __ldg(g_quat + b*4 + 1);
    float qz = __ldg(g_quat + b*4 + 2), qw = __ldg(g_quat + b*4 + 3);
    float rn = rsqrtf(qx*qx + qy*qy + qz*qz + qw*qw);
    qx *= rn; qy *= rn; qz *= rn; qw *= rn;
    float r00 = 1.f - 2.f*(qy*qy + qz*qz), r01 = 2.f*(qx*qy - qz*qw), r02 = 2.f*(qx*qz + qy*qw);
    float r10 = 2.f*(qx*qy + qz*qw), r11 = 1.f - 2.f*(qx*qx + qz*qz), r12 = 2.f*(qy*qz - qx*qw);
    float r20 = 2.f*(qx*qz - qy*qw), r21 = 2.f*(qy*qz + qx*qw), r22 = 1.f - 2.f*(qx*qx + qy*qy);

    float px = __ldg(g_pos + b*3 + 0), py = __ldg(g_pos + b*3 + 1), pz = __ldg(g_pos + b*3 + 2);
    float lox = __ldg(g_aabb + b*6 + 0), loy = __ldg(g_aabb + b*6 + 1), loz = __ldg(g_aabb + b*6 + 2);
    float hix = __ldg(g_aabb + b*6 + 3), hiy = __ldg(g_aabb + b*6 + 4), hiz = __ldg(g_aabb + b*6 + 5);

    // voxel center (meshgrid 'ij': n = i*64 + j*8 + k)
    float ci = (float)(idx >> 6)       + 0.5f;
    float cj = (float)((idx >> 3) & 7) + 0.5f;
    float ck = (float)(idx & 7)        + 0.5f;
    float vx = (ci * 0.125f) * (hix - lox) + lox;
    float vy = (cj * 0.125f) * (hiy - loy) + loy;
    float vz = (ck * 0.125f) * (hiz - loz) + loz;
    float e = expf(__ldg(g_pls));

    u64 h[8];
    #pragma unroll
    for (int t = 0; t < 8; t++) h[t] = *(const u64*)(c_b1 + 2*t);

    accw<0>(h, r00*vx + r01*vy + r02*vz + px);
    accw<1>(h, r10*vx + r11*vy + r12*vz + py);
    accw<2>(h, r20*vx + r21*vy + r22*vz + pz);
    accw<67>(h, px*e);
    accw<68>(h, py*e);
    accw<69>(h, pz*e);
    accw<70>(h, r00);
    accw<71>(h, r01);
    accw<72>(h, r02);
    accw<73>(h, r10);
    accw<74>(h, r11);
    accw<75>(h, r12);
    accw<76>(h, r20);
    accw<77>(h, r21);
    accw<78>(h, r22);

    __syncwarp(FULL);

    // ---- consume phase 0 (feature rows 3..34) ----
    const float* row = sz + lane*ZSTRIDE;
    #pragma unroll
    for (int t = 0; t < 8; t++){
        float4 a = *(const float4*)(row + 4*t);
        accr(h, a.x, c_w1 + (3 + 4*t + 0)*16);
        accr(h, a.y, c_w1 + (3 + 4*t + 1)*16);
        accr(h, a.z, c_w1 + (3 + 4*t + 2)*16);
        accr(h, a.w, c_w1 + (3 + 4*t + 3)*16);
    }
    __syncwarp(FULL);

    // ---- phase 1 staging: cols 32..63 ----
    #pragma unroll
    for (int r = 0; r < 32; r++){
        int ir = __shfl_sync(FULL, idx, r);
        sz[r*ZSTRIDE + lane] = __ldcs(xzb + (ir << 6) + 32 + lane);
    }
    __syncwarp(FULL);

    // ---- consume phase 1 (feature rows 35..66) ----
    #pragma unroll
    for (int t = 0; t < 8; t++){
        float4 a = *(const float4*)(row + 4*t);
        accr(h, a.x, c_w1 + (35 + 4*t + 0)*16);
        accr(h, a.y, c_w1 + (35 + 4*t + 1)*16);
        accr(h, a.z, c_w1 + (35 + 4*t + 2)*16);
        accr(h, a.w, c_w1 + (35 + 4*t + 3)*16);
    }

    // ---- relu + LN(16) per lane, x2, butterfly-sum over the 32 samples ----
    float v[16];
    #pragma unroll
    for (int t = 0; t < 8; t++) upk2(h[t], v[2*t], v[2*t+1]);
    float m = 0.f;
    #pragma unroll
    for (int j = 0; j < 16; j++){ v[j] = fmaxf(v[j], 0.f); m += v[j]; }
    m *= 0.0625f;
    float var = 0.f;
    #pragma unroll
    for (int j = 0; j < 16; j++){ float d = v[j] - m; var += d*d; }
    var *= 0.0625f;
    float is = rsqrtf(var + 1e-6f);
    #pragma unroll
    for (int j = 0; j < 16; j++){
        float y = (v[j] - m) * is * c_g1[j] + c_be1[j];
        y += y;                                  // z = z + z
        y += __shfl_xor_sync(FULL, y, 16);
        y += __shfl_xor_sync(FULL, y, 8);
        y += __shfl_xor_sync(FULL, y, 4);
        y += __shfl_xor_sync(FULL, y, 2);
        y += __shfl_xor_sync(FULL, y, 1);
        v[j] = y;
    }

    // ---- head: lane = channel, split accumulators ----
    {
        float a0 = __ldg(g_b2a + lane), a1 = 0.f, a2 = 0.f, a3 = 0.f;
        #pragma unroll
        for (int i = 0; i < 16; i += 4){
            a0 = fmaf(v[i+0], __ldg(g_w2a + (i+0)*32 + lane), a0);
            a1 = fmaf(v[i+1], __ldg(g_w2a + (i+1)*32 + lane), a1);
            a2 = fmaf(v[i+2], __ldg(g_w2a + (i+2)*32 + lane), a2);
            a3 = fmaf(v[i+3], __ldg(g_w2a + (i+3)*32 + lane), a3);
        }
        float a = (a0 + a1) + (a2 + a3);
        a = fmaxf(a, 0.f);
        float ma = wsum(a) * 0.03125f;
        float da = a - ma;
        float va = wsum(da*da) * 0.03125f;
        float ya = da * rsqrtf(va + 1e-6f) * __ldg(g_g2a + lane) + __ldg(g_be2a + lane);

        float c0 = __ldg(g_b2b + lane), c1 = 0.f, c2 = 0.f, c3 = 0.f;
        #pragma unroll
        for (int i = 0; i < 32; i += 4){
            c0 = fmaf(__shfl_sync(FULL, ya, i+0), __ldg(g_w2b + (i+0)*32 + lane), c0);
            c1 = fmaf(__shfl_sync(FULL, ya, i+1), __ldg(g_w2b + (i+1)*32 + lane), c1);
            c2 = fmaf(__shfl_sync(FULL, ya, i+2), __ldg(g_w2b + (i+2)*32 + lane), c2);
            c3 = fmaf(__shfl_sync(FULL, ya, i+3), __ldg(g_w2b + (i+3)*32 + lane), c3);
        }
        float c = (c0 + c1) + (c2 + c3);
        c = fmaxf(c, 0.f);
        float mc = wsum(c) * 0.03125f;
        float dc = c - mc;
        float vc = wsum(dc*dc) * 0.03125f;
        float yb = dc * rsqrtf(vc + 1e-6f) * __ldg(g_g2b + lane) + __ldg(g_be2b + lane);
        float zf = yb + ya;   // residual

        float o0 = (lane < 13) ? __ldg(g_bout + lane) : 0.f;
        float o1 = 0.f;
        #pragma unroll
        for (int i = 0; i < 32; i += 2){
            float zi0 = __shfl_sync(FULL, zf, i);
            float zi1 = __shfl_sync(FULL, zf, i+1);
            if (lane < 13){
                o0 = fmaf(zi0, __ldg(g_wout + (i  )*13 + lane), o0);
                o1 = fmaf(zi1, __ldg(g_wout + (i+1)*13 + lane), o1);
            }
        }
        if (lane < 13) g_out[b*13 + lane] = tanhf(o0 + o1);
    }
}

extern "C" void kernel_launch(void* const* d_in, const int* in_sizes, int n_in,
                              void* d_out, int out_size)
{
    (void)in_sizes; (void)n_in; (void)out_size;
    // layer-1 params -> constant bank (device-to-device async copies, graph-capturable)
    cudaMemcpyToSymbolAsync(c_w1,  d_in[6], 79*16*sizeof(float), 0, cudaMemcpyDeviceToDevice, 0);
    cudaMemcpyToSymbolAsync(c_b1,  d_in[7], 16*sizeof(float),    0, cudaMemcpyDeviceToDevice, 0);
    cudaMemcpyToSymbolAsync(c_g1,  d_in[8], 16*sizeof(float),    0, cudaMemcpyDeviceToDevice, 0);
    cudaMemcpyToSymbolAsync(c_be1, d_in[9], 16*sizeof(float),    0, cudaMemcpyDeviceToDevice, 0);

    plane_kernel<<<1024, 256>>>(
        (const float*)d_in[0],  (const float*)d_in[1],  (const float*)d_in[2],
        (const float*)d_in[3],  (const int*)  d_in[4],  (const float*)d_in[5],
        (const float*)d_in[10], (const float*)d_in[11],
        (const float*)d_in[12], (const float*)d_in[13], (const float*)d_in[14],
        (const float*)d_in[15], (const float*)d_in[16], (const float*)d_in[17],
        (const float*)d_in[18], (const float*)d_in[19],
        (float*)d_out);
}